// round 3
// baseline (speedup 1.0000x reference)
#include <cuda_runtime.h>
#include <stdint.h>

// RGBMem: NCE memory-bank kernel.
//   logits[b,k] = dot(memory[row(b,k)], x[b]) / T,  row(b,0)=y[b], else idx[b,k]
//   labels = zeros
//   new_memory = memory with rows y[b] := normalize(0.5*memory[y]+0.5*x[b])
// Output (float32): [logits (bsz*Kp1)] [labels gap] [memory (n_data*128)]
// Indices arrive as int32 (validated R2); sniff kept per-block for robustness.

#define T_INV (1.0f / 0.07f)

__device__ __forceinline__ long long load_index(const void* p, unsigned i,
                                                int is64) {
    if (is64) return ((const long long*)p)[i];
    return (long long)((const int*)p)[i];
}

__device__ __forceinline__ int sniff_is64(const void* idx) {
    const unsigned* w = (const unsigned*)idx;
    int is64 = 1;
    #pragma unroll
    for (int i = 0; i < 16; i++)
        if (w[2 * i + 1] != 0u) { is64 = 0; break; }
    return is64;
}

// ---------------------------------------------------------------------------
// Fused kernel: per block, warps [0,CW) stream-copy the memory table to the
// output (L2-bypassing hints), warps [CW,8) compute gathered dot-product
// logits (cached loads -> gather rows stay hot in L2).
// ---------------------------------------------------------------------------
__global__ void __launch_bounds__(256) fused_kernel(
    const float* __restrict__ x,
    const void* __restrict__ y,
    const void* __restrict__ idx,
    const float* __restrict__ memory,
    float* __restrict__ logits,
    const float4* __restrict__ mem4,
    float4* __restrict__ out_mem4,
    int bsz, unsigned Kp1, long long n_data, long long n4,
    int copy_warps) {
    __shared__ float4 xs[16 * 32];
    __shared__ int s_is64;
    int tid = threadIdx.x;
    if (tid == 0) s_is64 = sniff_is64(idx);
    int nx4 = bsz * 32;
    for (int i = tid; i < nx4; i += blockDim.x) xs[i] = ((const float4*)x)[i];
    __syncthreads();
    int is64 = s_is64;

    int warp = tid >> 5;
    int lane = tid & 31;
    int wpb = blockDim.x >> 5;

    if (warp < copy_warps) {
        // ---- copy role: streaming, evict-first in L2 ----
        long long cw = (long long)blockIdx.x * copy_warps + warp;
        long long ncw = (long long)gridDim.x * copy_warps;
        long long i = cw * 32 + lane;
        long long stride = ncw * 32;
        for (; i < n4; i += stride) {
            float4 v = __ldcs(mem4 + i);
            __stcs(out_mem4 + i, v);
        }
    } else {
        // ---- logits role: one warp per (b,k), cached gather ----
        int lw = warp - copy_warps;
        int lwpb = wpb - copy_warps;
        unsigned gw = (unsigned)blockIdx.x * lwpb + lw;
        unsigned ngw = (unsigned)gridDim.x * lwpb;
        unsigned total = (unsigned)bsz * Kp1;
        for (unsigned i = gw; i < total; i += ngw) {
            unsigned b = i / Kp1;
            unsigned k = i - b * Kp1;
            long long row = (k == 0) ? load_index(y, b, is64)
                                     : load_index(idx, i, is64);
            row = row < 0 ? 0 : (row >= n_data ? n_data - 1 : row);
            float4 m = __ldg((const float4*)(memory + row * 128) + lane);
            float4 xv = xs[b * 32 + lane];
            float s = m.x * xv.x + m.y * xv.y + m.z * xv.z + m.w * xv.w;
            #pragma unroll
            for (int off = 16; off; off >>= 1)
                s += __shfl_xor_sync(0xffffffffu, s, off);
            if (lane == 0) logits[i] = s * T_INV;
        }
    }
}

// ---------------------------------------------------------------------------
// EMA update + normalize of the bsz touched rows; zero the labels gap.
// ---------------------------------------------------------------------------
__global__ void update_kernel(const float* __restrict__ x,
                              const void* __restrict__ y,
                              const void* __restrict__ idx,
                              const float* __restrict__ memory,
                              float* __restrict__ out_mem,
                              float* __restrict__ out_labels,
                              int label_elems, long long n_data) {
    int b = blockIdx.x;
    int t = threadIdx.x;
    __shared__ int s_is64;
    if (t == 0) s_is64 = sniff_is64(idx);
    __syncthreads();
    long long row = load_index(y, (unsigned)b, s_is64);
    row = row < 0 ? 0 : (row >= n_data ? n_data - 1 : row);

    float v = memory[row * 128 + t] * 0.5f + x[b * 128 + t] * 0.5f;

    float s = v * v;
    #pragma unroll
    for (int off = 16; off; off >>= 1)
        s += __shfl_xor_sync(0xffffffffu, s, off);
    __shared__ float ws[4];
    if ((t & 31) == 0) ws[t >> 5] = s;
    __syncthreads();
    float tot = ws[0] + ws[1] + ws[2] + ws[3];
    float denom = fmaxf(sqrtf(tot), 1e-12f);

    out_mem[row * 128 + t] = v / denom;

    if (b == 0 && t < label_elems) out_labels[t] = 0.0f;
}

// ---------------------------------------------------------------------------
extern "C" void kernel_launch(void* const* d_in, const int* in_sizes, int n_in,
                              void* d_out, int out_size) {
    const float* x      = (const float*)d_in[0];   // [bsz, 128]
    const void*  y      = d_in[1];                 // [bsz]
    const void*  idx    = d_in[2];                 // [bsz, K+1]
    const float* memory = (const float*)d_in[3];   // [n_data, 128]

    int bsz = in_sizes[1];
    unsigned Kp1 = (unsigned)(in_sizes[2] / bsz);
    long long mem_elems = (long long)in_sizes[3];
    long long n_data = mem_elems / 128;
    long long logits_elems = (long long)bsz * Kp1;

    float* out = (float*)d_out;
    long long mem_off = (long long)out_size - mem_elems;
    if (mem_off < logits_elems) mem_off = logits_elems;
    float* out_mem = out + mem_off;
    float* out_labels = out + logits_elems;
    int label_elems = (int)(mem_off - logits_elems);

    // 1) fused copy + logits (concurrent, both DRAM-bound roles share BW)
    fused_kernel<<<1184, 256>>>(x, y, idx, memory, out,
                                (const float4*)memory, (float4*)out_mem,
                                bsz, Kp1, n_data, mem_elems / 4,
                                /*copy_warps=*/4);
    // 2) EMA + normalize scatter, zero labels (stream-ordered after copy)
    update_kernel<<<bsz, 128>>>(x, y, idx, memory, out_mem, out_labels,
                                label_elems, n_data);
}

// round 5
// speedup vs baseline: 1.5459x; 1.5459x over previous
#include <cuda_runtime.h>
#include <stdint.h>

// RGBMem: NCE memory-bank kernel, inverted-index single-sweep formulation.
//   logits[b,k] = dot(memory[row(b,k)], x[b]) / T,  row(b,0)=y[b], else idx[b,k]
//   labels = zeros
//   new_memory = memory with rows y[b] := normalize(0.5*memory[y]+0.5*x[b])
// Output (float32): [logits (bsz*Kp1)] [labels gap] [memory (n_data*128)]
// Strategy: build row -> logit-slot inverted lists, then ONE streaming sweep
// of the table does copy + all dot products (table read once, not 3.1x).

#define T_INV (1.0f / 0.07f)
#define MAX_ROWS 524288
#define CAP 48

__device__ unsigned g_count[MAX_ROWS];            // 2 MB (used prefix)
__device__ unsigned g_list[(size_t)MAX_ROWS * CAP]; // 96 MB scratch

__device__ __forceinline__ long long load_index(const void* p, unsigned i,
                                                int is64) {
    if (is64) return ((const long long*)p)[i];
    return (long long)((const int*)p)[i];
}

__device__ __forceinline__ int sniff_is64(const void* idx) {
    const unsigned* w = (const unsigned*)idx;
    int is64 = 1;
    #pragma unroll
    for (int i = 0; i < 16; i++)
        if (w[2 * i + 1] != 0u) { is64 = 0; break; }
    return is64;
}

// ---------------------------------------------------------------------------
__global__ void zero_counts_kernel(long long n) {
    long long i = (long long)blockIdx.x * blockDim.x + threadIdx.x;
    long long stride = (long long)gridDim.x * blockDim.x;
    for (; i < n; i += stride) g_count[i] = 0u;
}

// ---------------------------------------------------------------------------
// Build inverted lists: one thread per logit slot i = b*Kp1 + k.
// Overflow beyond CAP (practically impossible, Poisson mean ~2.1) computes
// the logit directly so correctness never depends on CAP.
// ---------------------------------------------------------------------------
__global__ void build_kernel(const float* __restrict__ x,
                             const void* __restrict__ y,
                             const void* __restrict__ idx,
                             const float* __restrict__ memory,
                             float* __restrict__ logits,
                             int bsz, unsigned Kp1, long long n_data) {
    __shared__ int s_is64;
    if (threadIdx.x == 0) s_is64 = sniff_is64(idx);
    __syncthreads();
    int is64 = s_is64;

    unsigned total = (unsigned)bsz * Kp1;
    unsigned i = blockIdx.x * blockDim.x + threadIdx.x;
    unsigned stride = gridDim.x * blockDim.x;
    for (; i < total; i += stride) {
        unsigned b = i / Kp1;
        unsigned k = i - b * Kp1;
        long long row = (k == 0) ? load_index(y, b, is64)
                                 : load_index(idx, i, is64);
        row = row < 0 ? 0 : (row >= n_data ? n_data - 1 : row);
        unsigned p = atomicAdd(&g_count[row], 1u);
        if (p < CAP) {
            g_list[(size_t)row * CAP + p] = i;
        } else {
            // direct fallback (never expected to run)
            const float* mr = memory + row * 128;
            const float* xr = x + b * 128;
            float s = 0.0f;
            for (int d = 0; d < 128; d++) s += __ldg(mr + d) * __ldg(xr + d);
            logits[i] = s * T_INV;
        }
    }
}

// ---------------------------------------------------------------------------
// Single streaming sweep: one warp per table row. Copy the 512B row to the
// output (streaming stores) and compute every logit that references it while
// it sits in registers. x (8KB) staged in shared.
// ---------------------------------------------------------------------------
__global__ void __launch_bounds__(256) sweep_kernel(
    const float* __restrict__ x,
    const float4* __restrict__ mem4,
    float4* __restrict__ out_mem4,
    float* __restrict__ logits,
    int bsz, unsigned Kp1, long long n_data) {
    __shared__ float4 xs[16 * 32];
    int tid = threadIdx.x;
    int nx4 = bsz * 32;
    for (int i = tid; i < nx4; i += blockDim.x) xs[i] = ((const float4*)x)[i];
    __syncthreads();

    int lane = tid & 31;
    long long warp = ((long long)blockIdx.x * blockDim.x + tid) >> 5;
    long long nwarps = ((long long)gridDim.x * blockDim.x) >> 5;

    for (long long r = warp; r < n_data; r += nwarps) {
        float4 m = __ldcs(mem4 + r * 32 + lane);   // read once, don't cache
        __stcs(out_mem4 + r * 32 + lane, m);       // streaming copy-out

        unsigned c = g_count[r];                   // broadcast load
        if (c > CAP) c = CAP;
        const unsigned* lst = g_list + (size_t)r * CAP;
        for (unsigned e = 0; e < c; e++) {
            unsigned i = lst[e];                   // broadcast load
            unsigned b = i / Kp1;
            float4 xv = xs[b * 32 + lane];
            float s = m.x * xv.x + m.y * xv.y + m.z * xv.z + m.w * xv.w;
            #pragma unroll
            for (int off = 16; off; off >>= 1)
                s += __shfl_xor_sync(0xffffffffu, s, off);
            if (lane == 0) logits[i] = s * T_INV;
        }
    }
}

// ---------------------------------------------------------------------------
// Fallback path kernels (R2-proven) in case n_data > MAX_ROWS.
// ---------------------------------------------------------------------------
__global__ void copy_mem_kernel(const float4* __restrict__ src,
                                float4* __restrict__ dst, long long n4) {
    long long i = (long long)blockIdx.x * blockDim.x + threadIdx.x;
    long long stride = (long long)gridDim.x * blockDim.x;
    for (; i < n4; i += stride) dst[i] = src[i];
}

__global__ void logits_kernel(const float* __restrict__ x,
                              const void* __restrict__ y,
                              const void* __restrict__ idx,
                              const float* __restrict__ memory,
                              float* __restrict__ logits,
                              int bsz, unsigned Kp1, long long n_data) {
    __shared__ float4 xs[16 * 32];
    __shared__ int s_is64;
    int tid = threadIdx.x;
    if (tid == 0) s_is64 = sniff_is64(idx);
    int nx4 = bsz * 32;
    for (int i = tid; i < nx4; i += blockDim.x) xs[i] = ((const float4*)x)[i];
    __syncthreads();
    int is64 = s_is64;

    int lane = tid & 31;
    unsigned warp = (blockIdx.x * blockDim.x + tid) >> 5;
    unsigned nwarps = (gridDim.x * blockDim.x) >> 5;
    unsigned total = (unsigned)bsz * Kp1;

    for (unsigned i = warp; i < total; i += nwarps) {
        unsigned b = i / Kp1;
        unsigned k = i - b * Kp1;
        long long row = (k == 0) ? load_index(y, b, is64)
                                 : load_index(idx, i, is64);
        row = row < 0 ? 0 : (row >= n_data ? n_data - 1 : row);
        float4 m = __ldg((const float4*)(memory + row * 128) + lane);
        float4 xv = xs[b * 32 + lane];
        float s = m.x * xv.x + m.y * xv.y + m.z * xv.z + m.w * xv.w;
        #pragma unroll
        for (int off = 16; off; off >>= 1)
            s += __shfl_xor_sync(0xffffffffu, s, off);
        if (lane == 0) logits[i] = s * T_INV;
    }
}

// ---------------------------------------------------------------------------
// EMA update + normalize of the bsz touched rows; zero the labels gap.
// ---------------------------------------------------------------------------
__global__ void update_kernel(const float* __restrict__ x,
                              const void* __restrict__ y,
                              const void* __restrict__ idx,
                              const float* __restrict__ memory,
                              float* __restrict__ out_mem,
                              float* __restrict__ out_labels,
                              int label_elems, long long n_data) {
    int b = blockIdx.x;
    int t = threadIdx.x;
    __shared__ int s_is64;
    if (t == 0) s_is64 = sniff_is64(idx);
    __syncthreads();
    long long row = load_index(y, (unsigned)b, s_is64);
    row = row < 0 ? 0 : (row >= n_data ? n_data - 1 : row);

    float v = memory[row * 128 + t] * 0.5f + x[b * 128 + t] * 0.5f;

    float s = v * v;
    #pragma unroll
    for (int off = 16; off; off >>= 1)
        s += __shfl_xor_sync(0xffffffffu, s, off);
    __shared__ float ws[4];
    if ((t & 31) == 0) ws[t >> 5] = s;
    __syncthreads();
    float tot = ws[0] + ws[1] + ws[2] + ws[3];
    float denom = fmaxf(sqrtf(tot), 1e-12f);

    out_mem[row * 128 + t] = v / denom;

    if (b == 0 && t < label_elems) out_labels[t] = 0.0f;
}

// ---------------------------------------------------------------------------
extern "C" void kernel_launch(void* const* d_in, const int* in_sizes, int n_in,
                              void* d_out, int out_size) {
    const float* x      = (const float*)d_in[0];   // [bsz, 128]
    const void*  y      = d_in[1];                 // [bsz]
    const void*  idx    = d_in[2];                 // [bsz, K+1]
    const float* memory = (const float*)d_in[3];   // [n_data, 128]

    int bsz = in_sizes[1];
    unsigned Kp1 = (unsigned)(in_sizes[2] / bsz);
    long long mem_elems = (long long)in_sizes[3];
    long long n_data = mem_elems / 128;
    long long logits_elems = (long long)bsz * Kp1;

    float* out = (float*)d_out;
    long long mem_off = (long long)out_size - mem_elems;
    if (mem_off < logits_elems) mem_off = logits_elems;
    float* out_mem = out + mem_off;
    float* out_labels = out + logits_elems;
    int label_elems = (int)(mem_off - logits_elems);

    if (n_data <= MAX_ROWS) {
        unsigned total = (unsigned)logits_elems;
        // 1) zero per-row counters
        zero_counts_kernel<<<512, 256>>>(n_data);
        // 2) build row -> slot inverted lists
        build_kernel<<<(total + 255) / 256, 256>>>(x, y, idx, memory, out,
                                                   bsz, Kp1, n_data);
        // 3) single streaming sweep: copy + all dot products
        sweep_kernel<<<2048, 256>>>(x, (const float4*)memory,
                                    (float4*)out_mem, out, bsz, Kp1, n_data);
    } else {
        copy_mem_kernel<<<2048, 256>>>((const float4*)memory,
                                       (float4*)out_mem, mem_elems / 4);
        logits_kernel<<<1184, 256>>>(x, y, idx, memory, out,
                                     bsz, Kp1, n_data);
    }
    // 4) EMA + normalize scatter, zero labels
    update_kernel<<<bsz, 128>>>(x, y, idx, memory, out_mem, out_labels,
                                label_elems, n_data);
}